// round 9
// baseline (speedup 1.0000x reference)
#include <cuda_runtime.h>
#include <cstdint>

#define NN 100000
#define DIM 64
#define NE 1250000
#define NE2 625000            // edges per scatter-thread pair
#define G_GEMM 391            // ceil(100000 / 256) tiles of 256 rows
#define ZERO_BLKS 1563        // ceil(1600000 float4 / 1024)
#define SCAT_BLKS 39063       // ceil(NE2*16 / 256)
#define SX_STRIDE 65
#define SMEM_BYTES ((256 * SX_STRIDE + 4096) * 4)   // 82944 B

// static device scratch — no allocation
__device__ float g_h2[NN * DIM];    // x @ W2
__device__ float g_acc[NN * DIM];   // neighbor sums

// ---------------------------------------------------------------------------
// 256-row GEMM tile, single matrix, broadcast-weight + R=2 row blocking.
// 8 warps: rowg = w>>1 (4 groups of 64 rows), colg = w&1 (32 cols).
// Lane owns rows (rowg*64+lane, +32), 32 cols -> 2 x 16 f32x2 accumulators.
// Per k: 8x LDS.128 warp-uniform weight broadcast + 2 scalar x reads
// feed 32 packed FFMA2.
// ---------------------------------------------------------------------------
__device__ __forceinline__ void gemm_tile256(
    int tile, const float* __restrict__ x, const float* __restrict__ W,
    float* __restrict__ hout, float* dsm)
{
    float* sx = dsm;                      // [256][65]
    float* sW = dsm + 256 * SX_STRIDE;    // [64][64] (k, c)

    const int tid = threadIdx.x;

    const float4* wv = (const float4*)W;
    #pragma unroll
    for (int i = tid; i < 1024; i += 256)
        ((float4*)sW)[i] = wv[i];

    const int rowBase = tile * 256;
    const float4* x4 = (const float4*)(x + (size_t)rowBase * DIM);
    #pragma unroll
    for (int i = tid; i < 4096; i += 256) {
        const int r = i >> 4;
        const int c = (i & 15) * 4;
        float4 v = make_float4(0.f, 0.f, 0.f, 0.f);
        if (rowBase + r < NN) v = x4[i];
        float* p = sx + r * SX_STRIDE + c;
        p[0] = v.x; p[1] = v.y; p[2] = v.z; p[3] = v.w;
    }
    __syncthreads();

    const int lane = tid & 31;
    const int w    = tid >> 5;
    const int rowg = w >> 1;
    const int colg = w & 1;

    const float* xr0 = sx + (rowg * 64 + lane) * SX_STRIDE;
    const float* xr1 = xr0 + 32 * SX_STRIDE;
    const float* wbase = sW + colg * 32;

    unsigned long long acc0[16], acc1[16];
    #pragma unroll
    for (int i = 0; i < 16; i++) { acc0[i] = 0ULL; acc1[i] = 0ULL; }

    #pragma unroll 4
    for (int k = 0; k < 64; ++k) {
        const float xs0 = xr0[k];
        const float xs1 = xr1[k];
        unsigned long long xa, xb;
        asm("mov.b64 %0, {%1, %1};" : "=l"(xa) : "f"(xs0));
        asm("mov.b64 %0, {%1, %1};" : "=l"(xb) : "f"(xs1));
        const ulonglong2* wr = (const ulonglong2*)(wbase + k * 64);
        #pragma unroll
        for (int i = 0; i < 8; ++i) {
            ulonglong2 wq = wr[i];   // 4 weight floats, broadcast LDS.128
            asm("fma.rn.f32x2 %0, %1, %2, %0;" : "+l"(acc0[2 * i])     : "l"(wq.x), "l"(xa));
            asm("fma.rn.f32x2 %0, %1, %2, %0;" : "+l"(acc0[2 * i + 1]) : "l"(wq.y), "l"(xa));
            asm("fma.rn.f32x2 %0, %1, %2, %0;" : "+l"(acc1[2 * i])     : "l"(wq.x), "l"(xb));
            asm("fma.rn.f32x2 %0, %1, %2, %0;" : "+l"(acc1[2 * i + 1]) : "l"(wq.y), "l"(xb));
        }
    }

    const int r0 = rowBase + rowg * 64 + lane;
    const int r1 = r0 + 32;
    if (r0 < NN) {
        unsigned long long* o = (unsigned long long*)(hout + (size_t)r0 * DIM + colg * 32);
        #pragma unroll
        for (int i = 0; i < 16; ++i) o[i] = acc0[i];
    }
    if (r1 < NN) {
        unsigned long long* o = (unsigned long long*)(hout + (size_t)r1 * DIM + colg * 32);
        #pragma unroll
        for (int i = 0; i < 16; ++i) o[i] = acc1[i];
    }
}

// ---------------------------------------------------------------------------
// Phase A: h2 = x@W2 (blocks [0, G_GEMM)), zero g_acc (remaining blocks).
// ---------------------------------------------------------------------------
__global__ __launch_bounds__(256) void phaseA(
    const float* __restrict__ x, const float* __restrict__ W2,
    float* __restrict__ h2, float* __restrict__ acc)
{
    extern __shared__ float dsm[];
    const int b = blockIdx.x;
    if (b < G_GEMM) {
        gemm_tile256(b, x, W2, h2, dsm);
    } else {
        const int bz = b - G_GEMM;
        const float4 z = make_float4(0.f, 0.f, 0.f, 0.f);
        #pragma unroll
        for (int i = 0; i < 4; ++i) {
            const int idx = bz * 1024 + i * 256 + threadIdx.x;
            if (idx < NN * DIM / 4) ((float4*)acc)[idx] = z;
        }
    }
}

// ---------------------------------------------------------------------------
// Phase B: gemm-h1 blocks co-resident with scatter blocks, one launch.
// First 2*G_GEMM blocks interleave (even -> gemm tile b/2, odd -> scatter
// chunk b/2); remaining blocks continue scatter chunks.
// Scatter: 16 threads/edge-pair; thread handles edges (e, e+NE2), one float4
// lane each, gathers issued before reds for MLP.
// ---------------------------------------------------------------------------
__global__ __launch_bounds__(256) void phaseB(
    const float* __restrict__ x, const float* __restrict__ W1,
    float* __restrict__ h1,
    const int* __restrict__ src, const int* __restrict__ dst,
    const float* __restrict__ h2, float* __restrict__ acc)
{
    extern __shared__ float dsm[];
    const int b = blockIdx.x;

    int sblk;
    if (b < 2 * G_GEMM) {
        if ((b & 1) == 0) { gemm_tile256(b >> 1, x, W1, h1, dsm); return; }
        sblk = b >> 1;
    } else {
        sblk = G_GEMM + (b - 2 * G_GEMM);
    }

    const long long gid = (long long)sblk * 256 + threadIdx.x;
    const int e = (int)(gid >> 4);
    const int c = (int)(gid & 15);
    if (e >= NE2) return;

    const int e1 = e + NE2;
    const int s0 = __ldg(&src[e]);
    const int d0 = __ldg(&dst[e]);
    const int s1 = __ldg(&src[e1]);
    const int d1 = __ldg(&dst[e1]);

    const float4* h2v = (const float4*)h2;
    float4 v0 = h2v[(size_t)s0 * 16 + c];
    float4 v1 = h2v[(size_t)s1 * 16 + c];

    float* p0 = acc + (size_t)d0 * DIM + c * 4;
    float* p1 = acc + (size_t)d1 * DIM + c * 4;
    asm volatile("red.global.add.v4.f32 [%0], {%1, %2, %3, %4};"
                 :: "l"(p0), "f"(v0.x), "f"(v0.y), "f"(v0.z), "f"(v0.w) : "memory");
    asm volatile("red.global.add.v4.f32 [%0], {%1, %2, %3, %4};"
                 :: "l"(p1), "f"(v1.x), "f"(v1.y), "f"(v1.z), "f"(v1.w) : "memory");
}

// ---------------------------------------------------------------------------
// Phase C: out = relu(h1 + acc), vectorized.
// ---------------------------------------------------------------------------
__global__ __launch_bounds__(256) void add_relu(
    float4* __restrict__ out, const float4* __restrict__ acc, int n4)
{
    const int i = blockIdx.x * blockDim.x + threadIdx.x;
    if (i >= n4) return;
    float4 a = out[i];
    float4 bv = acc[i];
    a.x = fmaxf(a.x + bv.x, 0.f);
    a.y = fmaxf(a.y + bv.y, 0.f);
    a.z = fmaxf(a.z + bv.z, 0.f);
    a.w = fmaxf(a.w + bv.w, 0.f);
    out[i] = a;
}

// ---------------------------------------------------------------------------
// Inputs (metadata order): x [N,64] f32, edge_index [2,E] i32, W1 [64,64] f32,
// W2 [64,64] f32. Output: [N,64] f32.
// ---------------------------------------------------------------------------
extern "C" void kernel_launch(void* const* d_in, const int* in_sizes, int n_in,
                              void* d_out, int out_size)
{
    const float* x   = (const float*)d_in[0];
    const int*   ei  = (const int*)d_in[1];
    const float* W1  = (const float*)d_in[2];
    const float* W2  = (const float*)d_in[3];
    float*       out = (float*)d_out;

    const int* src = ei;        // edge_index[0]
    const int* dst = ei + NE;   // edge_index[1]

    float* h2;  cudaGetSymbolAddress((void**)&h2,  g_h2);
    float* acc; cudaGetSymbolAddress((void**)&acc, g_acc);

    cudaFuncSetAttribute(phaseA, cudaFuncAttributeMaxDynamicSharedMemorySize, SMEM_BYTES);
    cudaFuncSetAttribute(phaseB, cudaFuncAttributeMaxDynamicSharedMemorySize, SMEM_BYTES);

    // A: h2 = x@W2, acc = 0
    phaseA<<<G_GEMM + ZERO_BLKS, 256, SMEM_BYTES>>>(x, W2, h2, acc);

    // B: out = x@W1 (gemm blocks) || acc[dst] += h2[src] (scatter blocks)
    phaseB<<<G_GEMM + SCAT_BLKS, 256, SMEM_BYTES>>>(x, W1, out, src, dst, h2, acc);

    // C: out = relu(out + acc)
    const int n4 = NN * DIM / 4;
    add_relu<<<(n4 + 255) / 256, 256>>>((float4*)out, (const float4*)acc, n4);
}

// round 11
// speedup vs baseline: 1.6470x; 1.6470x over previous
#include <cuda_runtime.h>
#include <cuda_fp16.h>
#include <cstdint>

#define NN 100000
#define DIM 64
#define NE 1250000

// h2 = x @ W2 stored as fp16 (12.8 MB) — scatter is its only consumer
__device__ __half g_h2h[NN * DIM];

// ---------------------------------------------------------------------------
// Kernel 1: dual GEMM, occupancy-oriented tile.
// Block: 256 threads = 8 warps, 64 rows, both matrices.
//   warp w: mat = w>>2 (0: W1 -> h1 fp32, 1: W2 -> h2 fp16)
//           colg = w&3 -> cols [colg*16, +16)
// Lane owns rows (lane, lane+32), 16 cols -> 2 x 8 f32x2 accumulators.
// Per k: 4x LDS.128 warp-uniform weight broadcast + 2 scalar x reads
// feed 16 packed FFMA2. acc[2i],acc[2i+1] <- wr[i] (cols 4i..4i+3), i=0..3.
// smem: sx[64][65] + sW1[4096] + sW2[4096] = 49408 B; target 3 blocks/SM.
// ---------------------------------------------------------------------------
#define SX_STRIDE 65
#define SMEM_BYTES ((64 * SX_STRIDE + 4096 + 4096) * 4)

__global__ __launch_bounds__(256, 3) void gemm_dual(
    const float* __restrict__ x,
    const float* __restrict__ W1,
    const float* __restrict__ W2,
    float* __restrict__ h1,
    __half* __restrict__ h2h)
{
    extern __shared__ float dsm[];
    float* sx  = dsm;                      // [64][65]
    float* sW1 = dsm + 64 * SX_STRIDE;     // [64][64] (k, c)
    float* sW2 = sW1 + 4096;

    const int tid = threadIdx.x;

    const float4* w1v = (const float4*)W1;
    const float4* w2v = (const float4*)W2;
    #pragma unroll
    for (int i = tid; i < 1024; i += 256) {
        ((float4*)sW1)[i] = w1v[i];
        ((float4*)sW2)[i] = w2v[i];
    }

    const int rowBase = blockIdx.x * 64;
    const float4* x4 = (const float4*)(x + (size_t)rowBase * DIM);
    #pragma unroll
    for (int i = tid; i < 1024; i += 256) {
        const int r = i >> 4;
        const int c = (i & 15) * 4;
        float4 v = make_float4(0.f, 0.f, 0.f, 0.f);
        if (rowBase + r < NN) v = x4[i];
        float* p = sx + r * SX_STRIDE + c;
        p[0] = v.x; p[1] = v.y; p[2] = v.z; p[3] = v.w;
    }
    __syncthreads();

    const int lane = tid & 31;
    const int w    = tid >> 5;
    const int mat  = w >> 2;
    const int colg = w & 3;

    const float* xr0 = sx + lane * SX_STRIDE;
    const float* xr1 = xr0 + 32 * SX_STRIDE;
    const float* wbase = (mat ? sW2 : sW1) + colg * 16;

    unsigned long long acc0[8], acc1[8];
    #pragma unroll
    for (int i = 0; i < 8; i++) { acc0[i] = 0ULL; acc1[i] = 0ULL; }

    #pragma unroll 4
    for (int k = 0; k < 64; ++k) {
        const float xs0 = xr0[k];
        const float xs1 = xr1[k];
        unsigned long long xa, xb;
        asm("mov.b64 %0, {%1, %1};" : "=l"(xa) : "f"(xs0));
        asm("mov.b64 %0, {%1, %1};" : "=l"(xb) : "f"(xs1));
        const ulonglong2* wr = (const ulonglong2*)(wbase + k * 64);
        #pragma unroll
        for (int i = 0; i < 4; ++i) {
            ulonglong2 wq = wr[i];   // 4 weight floats (cols 4i..4i+3), LDS.128
            asm("fma.rn.f32x2 %0, %1, %2, %0;" : "+l"(acc0[2 * i])     : "l"(wq.x), "l"(xa));
            asm("fma.rn.f32x2 %0, %1, %2, %0;" : "+l"(acc0[2 * i + 1]) : "l"(wq.y), "l"(xa));
            asm("fma.rn.f32x2 %0, %1, %2, %0;" : "+l"(acc1[2 * i])     : "l"(wq.x), "l"(xb));
            asm("fma.rn.f32x2 %0, %1, %2, %0;" : "+l"(acc1[2 * i + 1]) : "l"(wq.y), "l"(xb));
        }
    }

    const int r0 = rowBase + lane;
    const int r1 = r0 + 32;

    if (mat == 0) {
        if (r0 < NN) {
            unsigned long long* o = (unsigned long long*)(h1 + (size_t)r0 * DIM + colg * 16);
            #pragma unroll
            for (int i = 0; i < 8; ++i) o[i] = acc0[i];
        }
        if (r1 < NN) {
            unsigned long long* o = (unsigned long long*)(h1 + (size_t)r1 * DIM + colg * 16);
            #pragma unroll
            for (int i = 0; i < 8; ++i) o[i] = acc1[i];
        }
    } else {
        // convert 8 f32x2 -> 8 f16x2 (d = {hi:a, lo:b} for cvt d,a,b) and store
        uint32_t p0[8], p1[8];
        #pragma unroll
        for (int i = 0; i < 8; ++i) {
            float lo, hi;
            asm("mov.b64 {%0, %1}, %2;" : "=f"(lo), "=f"(hi) : "l"(acc0[i]));
            asm("cvt.rn.f16x2.f32 %0, %1, %2;" : "=r"(p0[i]) : "f"(hi), "f"(lo));
            asm("mov.b64 {%0, %1}, %2;" : "=f"(lo), "=f"(hi) : "l"(acc1[i]));
            asm("cvt.rn.f16x2.f32 %0, %1, %2;" : "=r"(p1[i]) : "f"(hi), "f"(lo));
        }
        if (r0 < NN) {
            uint4* o = (uint4*)(h2h + (size_t)r0 * DIM + colg * 16);
            o[0] = make_uint4(p0[0], p0[1], p0[2], p0[3]);
            o[1] = make_uint4(p0[4], p0[5], p0[6], p0[7]);
        }
        if (r1 < NN) {
            uint4* o = (uint4*)(h2h + (size_t)r1 * DIM + colg * 16);
            o[0] = make_uint4(p1[0], p1[1], p1[2], p1[3]);
            o[1] = make_uint4(p1[4], p1[5], p1[6], p1[7]);
        }
    }
}

// ---------------------------------------------------------------------------
// Kernel 2: edge scatter, fp16 gather -> fp32 red.
// 8 threads per edge; each loads one uint4 (8 halves = 16B), converts to
// 2 float4, issues 2x red.global.add.v4.f32 into out (which holds h1).
// ---------------------------------------------------------------------------
__global__ __launch_bounds__(256) void scatter_edges(
    const int* __restrict__ src,
    const int* __restrict__ dst,
    const __half* __restrict__ h2h,
    float* __restrict__ out)
{
    const long long gid = (long long)blockIdx.x * blockDim.x + threadIdx.x;
    const int e = (int)(gid >> 3);
    const int c = (int)(gid & 7);
    if (e >= NE) return;

    const int s = __ldg(&src[e]);
    const int d = __ldg(&dst[e]);

    const uint4 hv = ((const uint4*)h2h)[(size_t)s * 8 + c];
    const float2 f0 = __half22float2(*(const __half2*)&hv.x);
    const float2 f1 = __half22float2(*(const __half2*)&hv.y);
    const float2 f2 = __half22float2(*(const __half2*)&hv.z);
    const float2 f3 = __half22float2(*(const __half2*)&hv.w);

    float* p = out + (size_t)d * DIM + c * 8;
    asm volatile("red.global.add.v4.f32 [%0], {%1, %2, %3, %4};"
                 :: "l"(p), "f"(f0.x), "f"(f0.y), "f"(f1.x), "f"(f1.y) : "memory");
    asm volatile("red.global.add.v4.f32 [%0], {%1, %2, %3, %4};"
                 :: "l"(p + 4), "f"(f2.x), "f"(f2.y), "f"(f3.x), "f"(f3.y) : "memory");
}

// ---------------------------------------------------------------------------
// Kernel 3: in-place ReLU, vectorized.
// ---------------------------------------------------------------------------
__global__ __launch_bounds__(256) void relu_inplace(float4* __restrict__ out, int n4)
{
    int i = blockIdx.x * blockDim.x + threadIdx.x;
    if (i >= n4) return;
    float4 v = out[i];
    v.x = fmaxf(v.x, 0.f);
    v.y = fmaxf(v.y, 0.f);
    v.z = fmaxf(v.z, 0.f);
    v.w = fmaxf(v.w, 0.f);
    out[i] = v;
}

// ---------------------------------------------------------------------------
// Inputs (metadata order): x [N,64] f32, edge_index [2,E] i32, W1 [64,64] f32,
// W2 [64,64] f32. Output: [N,64] f32.
// ---------------------------------------------------------------------------
extern "C" void kernel_launch(void* const* d_in, const int* in_sizes, int n_in,
                              void* d_out, int out_size)
{
    const float* x   = (const float*)d_in[0];
    const int*   ei  = (const int*)d_in[1];
    const float* W1  = (const float*)d_in[2];
    const float* W2  = (const float*)d_in[3];
    float*       out = (float*)d_out;

    const int* src = ei;        // edge_index[0]
    const int* dst = ei + NE;   // edge_index[1]

    __half* h2h;
    cudaGetSymbolAddress((void**)&h2h, g_h2h);

    cudaFuncSetAttribute(gemm_dual, cudaFuncAttributeMaxDynamicSharedMemorySize,
                         SMEM_BYTES);

    // 1) out = x@W1 (fully overwrites out), g_h2h = fp16(x@W2)
    gemm_dual<<<(NN + 63) / 64, 256, SMEM_BYTES>>>(x, W1, W2, out, h2h);

    // 2) out[dst] += h2h[src]  (8 threads per edge)
    const long long total = (long long)NE * 8;
    const int blocks = (int)((total + 255) / 256);
    scatter_edges<<<blocks, 256>>>(src, dst, h2h, out);

    // 3) relu in place
    const int n4 = NN * DIM / 4;
    relu_inplace<<<(n4 + 255) / 256, 256>>>((float4*)out, n4);
}

// round 13
// speedup vs baseline: 1.9283x; 1.1708x over previous
#include <cuda_runtime.h>
#include <cuda_fp16.h>
#include <cstdint>

#define NN 100000
#define DIM 64
#define NE 1250000

// h2 = x @ W2 stored as fp16 (12.8 MB) — scatter is its only consumer
__device__ __half g_h2h[NN * DIM];

// ---------------------------------------------------------------------------
// Kernel 1: dual GEMM, occupancy-oriented tile (unchanged from R11).
// Block: 256 threads = 8 warps, 64 rows, both matrices.
//   warp w: mat = w>>2 (0: W1 -> h1 fp32, 1: W2 -> h2 fp16)
//           colg = w&3 -> cols [colg*16, +16)
// Lane owns rows (lane, lane+32), 16 cols -> 2 x 8 f32x2 accumulators.
// smem: sx[64][65] + sW1[4096] + sW2[4096] = 49408 B; 3 blocks/SM.
// ---------------------------------------------------------------------------
#define SX_STRIDE 65
#define SMEM_BYTES ((64 * SX_STRIDE + 4096 + 4096) * 4)

__global__ __launch_bounds__(256, 3) void gemm_dual(
    const float* __restrict__ x,
    const float* __restrict__ W1,
    const float* __restrict__ W2,
    float* __restrict__ h1,
    __half* __restrict__ h2h)
{
    extern __shared__ float dsm[];
    float* sx  = dsm;                      // [64][65]
    float* sW1 = dsm + 64 * SX_STRIDE;     // [64][64] (k, c)
    float* sW2 = sW1 + 4096;

    const int tid = threadIdx.x;

    const float4* w1v = (const float4*)W1;
    const float4* w2v = (const float4*)W2;
    #pragma unroll
    for (int i = tid; i < 1024; i += 256) {
        ((float4*)sW1)[i] = w1v[i];
        ((float4*)sW2)[i] = w2v[i];
    }

    const int rowBase = blockIdx.x * 64;
    const float4* x4 = (const float4*)(x + (size_t)rowBase * DIM);
    #pragma unroll
    for (int i = tid; i < 1024; i += 256) {
        const int r = i >> 4;
        const int c = (i & 15) * 4;
        float4 v = make_float4(0.f, 0.f, 0.f, 0.f);
        if (rowBase + r < NN) v = x4[i];
        float* p = sx + r * SX_STRIDE + c;
        p[0] = v.x; p[1] = v.y; p[2] = v.z; p[3] = v.w;
    }
    __syncthreads();

    const int lane = tid & 31;
    const int w    = tid >> 5;
    const int mat  = w >> 2;
    const int colg = w & 3;

    const float* xr0 = sx + lane * SX_STRIDE;
    const float* xr1 = xr0 + 32 * SX_STRIDE;
    const float* wbase = (mat ? sW2 : sW1) + colg * 16;

    unsigned long long acc0[8], acc1[8];
    #pragma unroll
    for (int i = 0; i < 8; i++) { acc0[i] = 0ULL; acc1[i] = 0ULL; }

    #pragma unroll 4
    for (int k = 0; k < 64; ++k) {
        const float xs0 = xr0[k];
        const float xs1 = xr1[k];
        unsigned long long xa, xb;
        asm("mov.b64 %0, {%1, %1};" : "=l"(xa) : "f"(xs0));
        asm("mov.b64 %0, {%1, %1};" : "=l"(xb) : "f"(xs1));
        const ulonglong2* wr = (const ulonglong2*)(wbase + k * 64);
        #pragma unroll
        for (int i = 0; i < 4; ++i) {
            ulonglong2 wq = wr[i];   // 4 weight floats (cols 4i..4i+3), LDS.128
            asm("fma.rn.f32x2 %0, %1, %2, %0;" : "+l"(acc0[2 * i])     : "l"(wq.x), "l"(xa));
            asm("fma.rn.f32x2 %0, %1, %2, %0;" : "+l"(acc0[2 * i + 1]) : "l"(wq.y), "l"(xa));
            asm("fma.rn.f32x2 %0, %1, %2, %0;" : "+l"(acc1[2 * i])     : "l"(wq.x), "l"(xb));
            asm("fma.rn.f32x2 %0, %1, %2, %0;" : "+l"(acc1[2 * i + 1]) : "l"(wq.y), "l"(xb));
        }
    }

    const int r0 = rowBase + lane;
    const int r1 = r0 + 32;

    if (mat == 0) {
        if (r0 < NN) {
            unsigned long long* o = (unsigned long long*)(h1 + (size_t)r0 * DIM + colg * 16);
            #pragma unroll
            for (int i = 0; i < 8; ++i) o[i] = acc0[i];
        }
        if (r1 < NN) {
            unsigned long long* o = (unsigned long long*)(h1 + (size_t)r1 * DIM + colg * 16);
            #pragma unroll
            for (int i = 0; i < 8; ++i) o[i] = acc1[i];
        }
    } else {
        // convert 8 f32x2 -> 8 f16x2 (d = {hi:a, lo:b} for cvt d,a,b) and store
        uint32_t p0[8], p1[8];
        #pragma unroll
        for (int i = 0; i < 8; ++i) {
            float lo, hi;
            asm("mov.b64 {%0, %1}, %2;" : "=f"(lo), "=f"(hi) : "l"(acc0[i]));
            asm("cvt.rn.f16x2.f32 %0, %1, %2;" : "=r"(p0[i]) : "f"(hi), "f"(lo));
            asm("mov.b64 {%0, %1}, %2;" : "=f"(lo), "=f"(hi) : "l"(acc1[i]));
            asm("cvt.rn.f16x2.f32 %0, %1, %2;" : "=r"(p1[i]) : "f"(hi), "f"(lo));
        }
        if (r0 < NN) {
            uint4* o = (uint4*)(h2h + (size_t)r0 * DIM + colg * 16);
            o[0] = make_uint4(p0[0], p0[1], p0[2], p0[3]);
            o[1] = make_uint4(p0[4], p0[5], p0[6], p0[7]);
        }
        if (r1 < NN) {
            uint4* o = (uint4*)(h2h + (size_t)r1 * DIM + colg * 16);
            o[0] = make_uint4(p1[0], p1[1], p1[2], p1[3]);
            o[1] = make_uint4(p1[4], p1[5], p1[6], p1[7]);
        }
    }
}

// ---------------------------------------------------------------------------
// Kernel 2: edge scatter, fp16 gather -> fp32 red. 16 threads per edge.
// Lane c: uint2 load (8B = 4 halves; 16 lanes -> one 128B line per edge),
// convert to 4 floats, ONE red.global.add.v4.f32 at d*256B + c*16B
// (contiguous 256B RED footprint per edge — the proven fp32 shape).
// ---------------------------------------------------------------------------
__global__ __launch_bounds__(256) void scatter_edges(
    const int* __restrict__ src,
    const int* __restrict__ dst,
    const __half* __restrict__ h2h,
    float* __restrict__ out)
{
    const long long gid = (long long)blockIdx.x * blockDim.x + threadIdx.x;
    const int e = (int)(gid >> 4);
    const int c = (int)(gid & 15);
    if (e >= NE) return;

    const int s = __ldg(&src[e]);
    const int d = __ldg(&dst[e]);

    const uint2 hv = ((const uint2*)h2h)[(size_t)s * 16 + c];
    const float2 f0 = __half22float2(*(const __half2*)&hv.x);
    const float2 f1 = __half22float2(*(const __half2*)&hv.y);

    float* p = out + (size_t)d * DIM + c * 4;
    asm volatile("red.global.add.v4.f32 [%0], {%1, %2, %3, %4};"
                 :: "l"(p), "f"(f0.x), "f"(f0.y), "f"(f1.x), "f"(f1.y) : "memory");
}

// ---------------------------------------------------------------------------
// Kernel 3: in-place ReLU, vectorized.
// ---------------------------------------------------------------------------
__global__ __launch_bounds__(256) void relu_inplace(float4* __restrict__ out, int n4)
{
    int i = blockIdx.x * blockDim.x + threadIdx.x;
    if (i >= n4) return;
    float4 v = out[i];
    v.x = fmaxf(v.x, 0.f);
    v.y = fmaxf(v.y, 0.f);
    v.z = fmaxf(v.z, 0.f);
    v.w = fmaxf(v.w, 0.f);
    out[i] = v;
}

// ---------------------------------------------------------------------------
// Inputs (metadata order): x [N,64] f32, edge_index [2,E] i32, W1 [64,64] f32,
// W2 [64,64] f32. Output: [N,64] f32.
// ---------------------------------------------------------------------------
extern "C" void kernel_launch(void* const* d_in, const int* in_sizes, int n_in,
                              void* d_out, int out_size)
{
    const float* x   = (const float*)d_in[0];
    const int*   ei  = (const int*)d_in[1];
    const float* W1  = (const float*)d_in[2];
    const float* W2  = (const float*)d_in[3];
    float*       out = (float*)d_out;

    const int* src = ei;        // edge_index[0]
    const int* dst = ei + NE;   // edge_index[1]

    __half* h2h;
    cudaGetSymbolAddress((void**)&h2h, g_h2h);

    cudaFuncSetAttribute(gemm_dual, cudaFuncAttributeMaxDynamicSharedMemorySize,
                         SMEM_BYTES);

    // 1) out = x@W1 (fully overwrites out), g_h2h = fp16(x@W2)
    gemm_dual<<<(NN + 63) / 64, 256, SMEM_BYTES>>>(x, W1, W2, out, h2h);

    // 2) out[dst] += h2h[src]  (16 threads per edge)
    const long long total = (long long)NE * 16;
    const int blocks = (int)((total + 255) / 256);
    scatter_edges<<<blocks, 256>>>(src, dst, h2h, out);

    // 3) relu in place
    const int n4 = NN * DIM / 4;
    relu_inplace<<<(n4 + 255) / 256, 256>>>((float4*)out, n4);
}

// round 15
// speedup vs baseline: 2.1807x; 1.1309x over previous
#include <cuda_runtime.h>
#include <cuda_fp16.h>
#include <cstdint>

#define NN 100000
#define DIM 64
#define NE 1250000

// h2 = x @ W2 stored as fp16 (12.8 MB) — scatter is its only consumer
__device__ __half g_h2h[NN * DIM];

// ---------------------------------------------------------------------------
// Kernel 1: dual GEMM, 8x8 register tile, outer-product formulation.
// Block: 256 threads, tile = 128 rows x 128 cols (cols 0-63 = W1 -> h1,
// 64-127 = W2 -> h2 fp16). Thread (tr = tid>>4, tc = tid&15) owns
// rows {4tr..4tr+3, 64+4tr..+3} x cols {4tc..4tc+3, 64+4tc..+3}.
// smem: sxT[64][132] (x transposed, sxT[k][r]) + sW[64][128] = 66560 B.
// Per k: 2 LDS.128 a-frag (2 distinct addrs/warp ~ broadcast) +
//        2 LDS.128 b-frag (conflict-free phases) -> 32 FFMA2.
// ---------------------------------------------------------------------------
#define S_XT 132
#define SMEM_BYTES ((64 * S_XT + 64 * 128) * 4)   // 66560

__global__ __launch_bounds__(256, 2) void gemm_dual(
    const float* __restrict__ x,
    const float* __restrict__ W1,
    const float* __restrict__ W2,
    float* __restrict__ h1,
    __half* __restrict__ h2h)
{
    extern __shared__ float dsm[];
    float* sxT = dsm;                 // [64][132]  sxT[k][r]
    float* sW  = dsm + 64 * S_XT;     // [64][128]  cols 0-63 W1, 64-127 W2

    const int tid  = threadIdx.x;
    const int lane = tid & 31;
    const int w    = tid >> 5;
    const int rowBase = blockIdx.x * 128;

    // ---- stage weights: sW[k][c] (c<64: W1, c>=64: W2), float4, CF banks
    #pragma unroll
    for (int i = tid; i < 2048; i += 256) {
        const int m = i >> 10;           // 0 = W1, 1 = W2
        const int j = i & 1023;
        const int k = j >> 4;
        const int c = (j & 15) * 4;
        const float4 v = ((const float4*)(m ? W2 : W1))[j];
        *(float4*)(sW + k * 128 + m * 64 + c) = v;
    }

    // ---- stage x transposed: warp-task = (k-half, 4-row group).
    // Lanes read x[r][k0+lane] coalesced (4 rows), store STS.128 down sxT.
    #pragma unroll
    for (int iter = 0; iter < 8; ++iter) {
        const int task = iter * 8 + w;        // 0..63
        const int r0 = (task & 31) * 4;
        const int k  = (task >> 5) * 32 + lane;
        const int gr = rowBase + r0;
        float v0 = 0.f, v1 = 0.f, v2 = 0.f, v3 = 0.f;
        if (gr + 0 < NN) v0 = x[(size_t)(gr + 0) * DIM + k];
        if (gr + 1 < NN) v1 = x[(size_t)(gr + 1) * DIM + k];
        if (gr + 2 < NN) v2 = x[(size_t)(gr + 2) * DIM + k];
        if (gr + 3 < NN) v3 = x[(size_t)(gr + 3) * DIM + k];
        *(float4*)(sxT + k * S_XT + r0) = make_float4(v0, v1, v2, v3);
    }
    __syncthreads();

    const int tc = tid & 15;
    const int tr = tid >> 4;

    const float* pa = sxT + 4 * tr;
    const float* pb = sW + 4 * tc;

    unsigned long long acc[8][4];
    #pragma unroll
    for (int r = 0; r < 8; ++r)
        #pragma unroll
        for (int p = 0; p < 4; ++p) acc[r][p] = 0ULL;

    #pragma unroll 4
    for (int k = 0; k < 64; ++k) {
        const ulonglong2 A0 = *(const ulonglong2*)(pa + k * S_XT);        // rows 4tr..+3
        const ulonglong2 A1 = *(const ulonglong2*)(pa + k * S_XT + 64);   // rows 64+4tr..
        const ulonglong2 B0 = *(const ulonglong2*)(pb + k * 128);         // cols 4tc..+3 (W1)
        const ulonglong2 B1 = *(const ulonglong2*)(pb + k * 128 + 64);    // cols 64+4tc.. (W2)

        unsigned long long a2[8];
        {
            float lo, hi;
            asm("mov.b64 {%0,%1}, %2;" : "=f"(lo), "=f"(hi) : "l"(A0.x));
            asm("mov.b64 %0, {%1,%1};" : "=l"(a2[0]) : "f"(lo));
            asm("mov.b64 %0, {%1,%1};" : "=l"(a2[1]) : "f"(hi));
            asm("mov.b64 {%0,%1}, %2;" : "=f"(lo), "=f"(hi) : "l"(A0.y));
            asm("mov.b64 %0, {%1,%1};" : "=l"(a2[2]) : "f"(lo));
            asm("mov.b64 %0, {%1,%1};" : "=l"(a2[3]) : "f"(hi));
            asm("mov.b64 {%0,%1}, %2;" : "=f"(lo), "=f"(hi) : "l"(A1.x));
            asm("mov.b64 %0, {%1,%1};" : "=l"(a2[4]) : "f"(lo));
            asm("mov.b64 %0, {%1,%1};" : "=l"(a2[5]) : "f"(hi));
            asm("mov.b64 {%0,%1}, %2;" : "=f"(lo), "=f"(hi) : "l"(A1.y));
            asm("mov.b64 %0, {%1,%1};" : "=l"(a2[6]) : "f"(lo));
            asm("mov.b64 %0, {%1,%1};" : "=l"(a2[7]) : "f"(hi));
        }
        #pragma unroll
        for (int r = 0; r < 8; ++r) {
            asm("fma.rn.f32x2 %0, %1, %2, %0;" : "+l"(acc[r][0]) : "l"(a2[r]), "l"(B0.x));
            asm("fma.rn.f32x2 %0, %1, %2, %0;" : "+l"(acc[r][1]) : "l"(a2[r]), "l"(B0.y));
            asm("fma.rn.f32x2 %0, %1, %2, %0;" : "+l"(acc[r][2]) : "l"(a2[r]), "l"(B1.x));
            asm("fma.rn.f32x2 %0, %1, %2, %0;" : "+l"(acc[r][3]) : "l"(a2[r]), "l"(B1.y));
        }
    }

    // ---- epilogue: h1 = cols 4tc..+3 (STG.128), h2h = cols 4tc..+3 fp16 (8B)
    #pragma unroll
    for (int r = 0; r < 8; ++r) {
        const int gr = rowBase + ((r < 4) ? (4 * tr + r) : (64 + 4 * tr + r - 4));
        if (gr < NN) {
            ulonglong2 o1;
            o1.x = acc[r][0];
            o1.y = acc[r][1];
            *(ulonglong2*)(h1 + (size_t)gr * DIM + 4 * tc) = o1;

            float l0, h0, l1, hh1;
            uint32_t p0, p1;
            asm("mov.b64 {%0,%1}, %2;" : "=f"(l0), "=f"(h0) : "l"(acc[r][2]));
            asm("mov.b64 {%0,%1}, %2;" : "=f"(l1), "=f"(hh1) : "l"(acc[r][3]));
            asm("cvt.rn.f16x2.f32 %0, %1, %2;" : "=r"(p0) : "f"(h0), "f"(l0));
            asm("cvt.rn.f16x2.f32 %0, %1, %2;" : "=r"(p1) : "f"(hh1), "f"(l1));
            *(uint2*)(h2h + (size_t)gr * DIM + 4 * tc) = make_uint2(p0, p1);
        }
    }
}

// ---------------------------------------------------------------------------
// Kernel 2: edge scatter, fp16 gather -> fp32 red. 16 threads per edge.
// Lane c: uint2 load (8B = 4 halves), ONE red.global.add.v4.f32 at
// d*256B + c*16B (contiguous 256B RED footprint per edge).
// ---------------------------------------------------------------------------
__global__ __launch_bounds__(256) void scatter_edges(
    const int* __restrict__ src,
    const int* __restrict__ dst,
    const __half* __restrict__ h2h,
    float* __restrict__ out)
{
    const long long gid = (long long)blockIdx.x * blockDim.x + threadIdx.x;
    const int e = (int)(gid >> 4);
    const int c = (int)(gid & 15);
    if (e >= NE) return;

    const int s = __ldg(&src[e]);
    const int d = __ldg(&dst[e]);

    const uint2 hv = ((const uint2*)h2h)[(size_t)s * 16 + c];
    const float2 f0 = __half22float2(*(const __half2*)&hv.x);
    const float2 f1 = __half22float2(*(const __half2*)&hv.y);

    float* p = out + (size_t)d * DIM + c * 4;
    asm volatile("red.global.add.v4.f32 [%0], {%1, %2, %3, %4};"
                 :: "l"(p), "f"(f0.x), "f"(f0.y), "f"(f1.x), "f"(f1.y) : "memory");
}

// ---------------------------------------------------------------------------
// Kernel 3: in-place ReLU, vectorized.
// ---------------------------------------------------------------------------
__global__ __launch_bounds__(256) void relu_inplace(float4* __restrict__ out, int n4)
{
    int i = blockIdx.x * blockDim.x + threadIdx.x;
    if (i >= n4) return;
    float4 v = out[i];
    v.x = fmaxf(v.x, 0.f);
    v.y = fmaxf(v.y, 0.f);
    v.z = fmaxf(v.z, 0.f);
    v.w = fmaxf(v.w, 0.f);
    out[i] = v;
}

// ---------------------------------------------------------------------------
// Inputs (metadata order): x [N,64] f32, edge_index [2,E] i32, W1 [64,64] f32,
// W2 [64,64] f32. Output: [N,64] f32.
// ---------------------------------------------------------------------------
extern "C" void kernel_launch(void* const* d_in, const int* in_sizes, int n_in,
                              void* d_out, int out_size)
{
    const float* x   = (const float*)d_in[0];
    const int*   ei  = (const int*)d_in[1];
    const float* W1  = (const float*)d_in[2];
    const float* W2  = (const float*)d_in[3];
    float*       out = (float*)d_out;

    const int* src = ei;        // edge_index[0]
    const int* dst = ei + NE;   // edge_index[1]

    __half* h2h;
    cudaGetSymbolAddress((void**)&h2h, g_h2h);

    cudaFuncSetAttribute(gemm_dual, cudaFuncAttributeMaxDynamicSharedMemorySize,
                         SMEM_BYTES);

    // 1) out = x@W1 (fully overwrites out), g_h2h = fp16(x@W2)
    gemm_dual<<<(NN + 127) / 128, 256, SMEM_BYTES>>>(x, W1, W2, out, h2h);

    // 2) out[dst] += h2h[src]  (16 threads per edge)
    const long long total = (long long)NE * 16;
    const int blocks = (int)((total + 255) / 256);
    scatter_edges<<<blocks, 256>>>(src, dst, h2h, out);

    // 3) relu in place
    const int n4 = NN * DIM / 4;
    relu_inplace<<<(n4 + 255) / 256, 256>>>((float4*)out, n4);
}

// round 16
// speedup vs baseline: 2.3857x; 1.0940x over previous
#include <cuda_runtime.h>
#include <cuda_fp16.h>
#include <cstdint>

#define NN 100000
#define DIM 64
#define NE 1250000
#define NBLK 98                    // ceil(100000 / 1024) scan blocks

// static device scratch — no allocation
__device__ __half g_h2h[NN * DIM];   // h2 = x @ W2, fp16
__device__ int g_deg[NN];
__device__ int g_start[NN + 1];
__device__ int g_cursor[NN];
__device__ int g_esrc[NE];
__device__ int g_btot[NBLK];
__device__ int g_boff[NBLK];

// ---------------------------------------------------------------------------
// Kernel 1: dual GEMM, 8x8 register tile (unchanged from R15 winner).
// ---------------------------------------------------------------------------
#define S_XT 132
#define SMEM_BYTES ((64 * S_XT + 64 * 128) * 4)   // 66560

__global__ __launch_bounds__(256, 2) void gemm_dual(
    const float* __restrict__ x,
    const float* __restrict__ W1,
    const float* __restrict__ W2,
    float* __restrict__ h1,
    __half* __restrict__ h2h)
{
    extern __shared__ float dsm[];
    float* sxT = dsm;                 // [64][132]  sxT[k][r]
    float* sW  = dsm + 64 * S_XT;     // [64][128]  cols 0-63 W1, 64-127 W2

    const int tid  = threadIdx.x;
    const int lane = tid & 31;
    const int w    = tid >> 5;
    const int rowBase = blockIdx.x * 128;

    #pragma unroll
    for (int i = tid; i < 2048; i += 256) {
        const int m = i >> 10;
        const int j = i & 1023;
        const int k = j >> 4;
        const int c = (j & 15) * 4;
        const float4 v = ((const float4*)(m ? W2 : W1))[j];
        *(float4*)(sW + k * 128 + m * 64 + c) = v;
    }

    #pragma unroll
    for (int iter = 0; iter < 8; ++iter) {
        const int task = iter * 8 + w;
        const int r0 = (task & 31) * 4;
        const int k  = (task >> 5) * 32 + lane;
        const int gr = rowBase + r0;
        float v0 = 0.f, v1 = 0.f, v2 = 0.f, v3 = 0.f;
        if (gr + 0 < NN) v0 = x[(size_t)(gr + 0) * DIM + k];
        if (gr + 1 < NN) v1 = x[(size_t)(gr + 1) * DIM + k];
        if (gr + 2 < NN) v2 = x[(size_t)(gr + 2) * DIM + k];
        if (gr + 3 < NN) v3 = x[(size_t)(gr + 3) * DIM + k];
        *(float4*)(sxT + k * S_XT + r0) = make_float4(v0, v1, v2, v3);
    }
    __syncthreads();

    const int tc = tid & 15;
    const int tr = tid >> 4;
    const float* pa = sxT + 4 * tr;
    const float* pb = sW + 4 * tc;

    unsigned long long acc[8][4];
    #pragma unroll
    for (int r = 0; r < 8; ++r)
        #pragma unroll
        for (int p = 0; p < 4; ++p) acc[r][p] = 0ULL;

    #pragma unroll 4
    for (int k = 0; k < 64; ++k) {
        const ulonglong2 A0 = *(const ulonglong2*)(pa + k * S_XT);
        const ulonglong2 A1 = *(const ulonglong2*)(pa + k * S_XT + 64);
        const ulonglong2 B0 = *(const ulonglong2*)(pb + k * 128);
        const ulonglong2 B1 = *(const ulonglong2*)(pb + k * 128 + 64);

        unsigned long long a2[8];
        {
            float lo, hi;
            asm("mov.b64 {%0,%1}, %2;" : "=f"(lo), "=f"(hi) : "l"(A0.x));
            asm("mov.b64 %0, {%1,%1};" : "=l"(a2[0]) : "f"(lo));
            asm("mov.b64 %0, {%1,%1};" : "=l"(a2[1]) : "f"(hi));
            asm("mov.b64 {%0,%1}, %2;" : "=f"(lo), "=f"(hi) : "l"(A0.y));
            asm("mov.b64 %0, {%1,%1};" : "=l"(a2[2]) : "f"(lo));
            asm("mov.b64 %0, {%1,%1};" : "=l"(a2[3]) : "f"(hi));
            asm("mov.b64 {%0,%1}, %2;" : "=f"(lo), "=f"(hi) : "l"(A1.x));
            asm("mov.b64 %0, {%1,%1};" : "=l"(a2[4]) : "f"(lo));
            asm("mov.b64 %0, {%1,%1};" : "=l"(a2[5]) : "f"(hi));
            asm("mov.b64 {%0,%1}, %2;" : "=f"(lo), "=f"(hi) : "l"(A1.y));
            asm("mov.b64 %0, {%1,%1};" : "=l"(a2[6]) : "f"(lo));
            asm("mov.b64 %0, {%1,%1};" : "=l"(a2[7]) : "f"(hi));
        }
        #pragma unroll
        for (int r = 0; r < 8; ++r) {
            asm("fma.rn.f32x2 %0, %1, %2, %0;" : "+l"(acc[r][0]) : "l"(a2[r]), "l"(B0.x));
            asm("fma.rn.f32x2 %0, %1, %2, %0;" : "+l"(acc[r][1]) : "l"(a2[r]), "l"(B0.y));
            asm("fma.rn.f32x2 %0, %1, %2, %0;" : "+l"(acc[r][2]) : "l"(a2[r]), "l"(B1.x));
            asm("fma.rn.f32x2 %0, %1, %2, %0;" : "+l"(acc[r][3]) : "l"(a2[r]), "l"(B1.y));
        }
    }

    #pragma unroll
    for (int r = 0; r < 8; ++r) {
        const int gr = rowBase + ((r < 4) ? (4 * tr + r) : (64 + 4 * tr + r - 4));
        if (gr < NN) {
            ulonglong2 o1;
            o1.x = acc[r][0];
            o1.y = acc[r][1];
            *(ulonglong2*)(h1 + (size_t)gr * DIM + 4 * tc) = o1;

            float l0, h0, l1, hh1;
            uint32_t p0, p1;
            asm("mov.b64 {%0,%1}, %2;" : "=f"(l0), "=f"(h0) : "l"(acc[r][2]));
            asm("mov.b64 {%0,%1}, %2;" : "=f"(l1), "=f"(hh1) : "l"(acc[r][3]));
            asm("cvt.rn.f16x2.f32 %0, %1, %2;" : "=r"(p0) : "f"(h0), "f"(l0));
            asm("cvt.rn.f16x2.f32 %0, %1, %2;" : "=r"(p1) : "f"(hh1), "f"(l1));
            *(uint2*)(h2h + (size_t)gr * DIM + 4 * tc) = make_uint2(p0, p1);
        }
    }
}

// ---------------------------------------------------------------------------
// CSR-by-dst construction
// ---------------------------------------------------------------------------
__global__ __launch_bounds__(256) void zero_deg(int* __restrict__ deg)
{
    const int i = blockIdx.x * 256 + threadIdx.x;
    if (i < NN) deg[i] = 0;
}

__global__ __launch_bounds__(256) void hist_dst(
    const int* __restrict__ dst, int* __restrict__ deg)
{
    const int e = blockIdx.x * 256 + threadIdx.x;
    if (e < NE) atomicAdd(&deg[__ldg(&dst[e])], 1);
}

// block-local exclusive scan over 1024 bins (4 per thread)
__global__ __launch_bounds__(256) void scan_blocks(
    const int* __restrict__ deg, int* __restrict__ start, int* __restrict__ btot)
{
    __shared__ int s[256];
    const int tid  = threadIdx.x;
    const int base = blockIdx.x * 1024 + tid * 4;

    int d0 = (base + 0 < NN) ? deg[base + 0] : 0;
    int d1 = (base + 1 < NN) ? deg[base + 1] : 0;
    int d2 = (base + 2 < NN) ? deg[base + 2] : 0;
    int d3 = (base + 3 < NN) ? deg[base + 3] : 0;
    const int mysum = d0 + d1 + d2 + d3;
    s[tid] = mysum;
    __syncthreads();

    for (int off = 1; off < 256; off <<= 1) {
        int v = (tid >= off) ? s[tid - off] : 0;
        __syncthreads();
        s[tid] += v;
        __syncthreads();
    }
    const int excl = s[tid] - mysum;
    if (tid == 255) btot[blockIdx.x] = s[255];

    if (base + 0 < NN) start[base + 0] = excl;
    if (base + 1 < NN) start[base + 1] = excl + d0;
    if (base + 2 < NN) start[base + 2] = excl + d0 + d1;
    if (base + 3 < NN) start[base + 3] = excl + d0 + d1 + d2;
}

__global__ void scan_tots(const int* __restrict__ btot, int* __restrict__ boff)
{
    if (threadIdx.x == 0) {
        int acc = 0;
        for (int i = 0; i < NBLK; ++i) { boff[i] = acc; acc += btot[i]; }
    }
}

__global__ __launch_bounds__(256) void scan_add(
    int* __restrict__ start, const int* __restrict__ boff, int* __restrict__ cursor)
{
    const int off  = boff[blockIdx.x];
    const int base = blockIdx.x * 1024 + threadIdx.x * 4;
    #pragma unroll
    for (int j = 0; j < 4; ++j) {
        const int i = base + j;
        if (i < NN) { const int v = start[i] + off; start[i] = v; cursor[i] = v; }
    }
    if (blockIdx.x == 0 && threadIdx.x == 0) start[NN] = NE;
}

__global__ __launch_bounds__(256) void reorder_edges(
    const int* __restrict__ src, const int* __restrict__ dst,
    int* __restrict__ cursor, int* __restrict__ esrc)
{
    const int e = blockIdx.x * 256 + threadIdx.x;
    if (e < NE) {
        const int d   = __ldg(&dst[e]);
        const int pos = atomicAdd(&cursor[d], 1);
        esrc[pos] = __ldg(&src[e]);
    }
}

// ---------------------------------------------------------------------------
// Fused gather-reduce + add h1 + ReLU. 16 threads per dst row; lane c owns
// 4 floats (uint2 of fp16 in gather, float4 in out). No atomics.
// ---------------------------------------------------------------------------
__global__ __launch_bounds__(256) void gather_relu(
    const int* __restrict__ start, const int* __restrict__ esrc,
    const __half* __restrict__ h2h, float* __restrict__ out)
{
    const int g = blockIdx.x * 16 + (threadIdx.x >> 4);   // dst row
    const int c = threadIdx.x & 15;
    if (g >= NN) return;

    const int s0 = __ldg(&start[g]);
    const int s1 = __ldg(&start[g + 1]);

    float a0 = 0.f, a1 = 0.f, a2 = 0.f, a3 = 0.f;
    for (int i = s0; i < s1; ++i) {
        const int s = __ldg(&esrc[i]);
        const uint2 hv = __ldg((const uint2*)h2h + (size_t)s * 16 + c);
        const float2 f0 = __half22float2(*(const __half2*)&hv.x);
        const float2 f1 = __half22float2(*(const __half2*)&hv.y);
        a0 += f0.x; a1 += f0.y; a2 += f1.x; a3 += f1.y;
    }

    float4* p = (float4*)out + (size_t)g * 16 + c;
    float4 v = *p;
    v.x = fmaxf(v.x + a0, 0.f);
    v.y = fmaxf(v.y + a1, 0.f);
    v.z = fmaxf(v.z + a2, 0.f);
    v.w = fmaxf(v.w + a3, 0.f);
    *p = v;
}

// ---------------------------------------------------------------------------
// Inputs (metadata order): x [N,64] f32, edge_index [2,E] i32, W1 [64,64] f32,
// W2 [64,64] f32. Output: [N,64] f32.
// ---------------------------------------------------------------------------
extern "C" void kernel_launch(void* const* d_in, const int* in_sizes, int n_in,
                              void* d_out, int out_size)
{
    const float* x   = (const float*)d_in[0];
    const int*   ei  = (const int*)d_in[1];
    const float* W1  = (const float*)d_in[2];
    const float* W2  = (const float*)d_in[3];
    float*       out = (float*)d_out;

    const int* src = ei;        // edge_index[0]
    const int* dst = ei + NE;   // edge_index[1]

    __half* h2h;  cudaGetSymbolAddress((void**)&h2h,   g_h2h);
    int* deg;     cudaGetSymbolAddress((void**)&deg,   g_deg);
    int* startp;  cudaGetSymbolAddress((void**)&startp, g_start);
    int* cursor;  cudaGetSymbolAddress((void**)&cursor, g_cursor);
    int* esrc;    cudaGetSymbolAddress((void**)&esrc,  g_esrc);
    int* btot;    cudaGetSymbolAddress((void**)&btot,  g_btot);
    int* boff;    cudaGetSymbolAddress((void**)&boff,  g_boff);

    cudaFuncSetAttribute(gemm_dual, cudaFuncAttributeMaxDynamicSharedMemorySize,
                         SMEM_BYTES);

    // 1) out = x@W1, g_h2h = fp16(x@W2)
    gemm_dual<<<(NN + 127) / 128, 256, SMEM_BYTES>>>(x, W1, W2, out, h2h);

    // 2) CSR-by-dst: deg -> start (scan) -> esrc (reorder)
    zero_deg<<<(NN + 255) / 256, 256>>>(deg);
    hist_dst<<<(NE + 255) / 256, 256>>>(dst, deg);
    scan_blocks<<<NBLK, 256>>>(deg, startp, btot);
    scan_tots<<<1, 32>>>(btot, boff);
    scan_add<<<NBLK, 256>>>(startp, boff, cursor);
    reorder_edges<<<(NE + 255) / 256, 256>>>(src, dst, cursor, esrc);

    // 3) out = relu(out + segment_sum(h2h[esrc]))
    gather_relu<<<(NN + 15) / 16, 256>>>(startp, esrc, h2h, out);
}